// round 12
// baseline (speedup 1.0000x reference)
#include <cuda_runtime.h>

// Fixed problem constants: T=1024, N*C=16, in_features=2, D_out=512,
// decay=exp(-0.5). delay[d] = (max(v,0), max(-v,0)) with
//   d in [0,256):   v = d-256  -> gd = 256-d, gather feature 1, bcast feature 0
//   d in [256,512): v = d-255  -> gd = d-255, gather feature 0, bcast feature 1
#define TLEN 1024
#define NCH  16
#define PAD  256
#define YLEN (PAD + TLEN)         // 1280
#define TT   16                   // t-chunk per block
#define WIN  272                  // TT + 256 staged y window per plane
#define NBLK 1024                 // 16 nc * 64 t-chunks

#define DECAY   0.60653065971263342f      // exp(-0.5)
#define DECAY16 3.3546262790251185e-04f   // exp(-8) = decay^16
#define L2F16   (-11.541560327111708f)    // -8/ln(2): decay^(16L) = exp2(L2F16*L)

// y planes with 256 zero front-pad: g_y[f*NCH+nc][PAD+t]. A gather at t-gd<0
// reads a stored 0 -> reproduces the reference t<delay mask exactly.
__device__ float g_y[2 * NCH * YLEN];
__device__ int g_done;   // scan-complete counter (reset each run)
__device__ int g_fin;    // finish counter for reset

__global__ __launch_bounds__(256)
void jeffress_all(const float* __restrict__ x,
                  const float* __restrict__ weight,
                  float*       __restrict__ out) {
    __shared__ float pool[1032];          // scan: xs[1024]+cross; gather: ybuf[2][272]

    const int tid = threadIdx.x;
    const int bid = blockIdx.x;

    // ---------------- Gather-phase per-thread setup (pre-barrier) ----------
    const int nc = bid & (NCH - 1);
    const int t0 = (bid >> 4) << 4;              // t-chunk start
    const int d  = (tid & 127) << 2;             // 4 consecutive d
    const int tb = (tid >> 7) << 3;              // t octet: 0 or 8

    const float4 w4 = *reinterpret_cast<const float4*>(weight + d);

    // ---------------- Phase 1: blocks 0..31 scan one channel each ----------
    if (bid < 32) {
        const int ch = bid;                      // f = ch&1, nc_s = ch>>1
        float* plane = g_y + ((ch & 1) * NCH + (ch >> 1)) * YLEN;

        // Stage x[t] for this channel (4 strided loads per thread)
        #pragma unroll
        for (int i = 0; i < 4; i++) {
            const int t = tid + (i << 8);
            pool[t] = __ldg(x + t * 32 + ch);
        }
        // Zero the front pad
        plane[tid] = 0.0f;
        __syncthreads();

        // 64 lanes x 16 elems: serial recurrence + 2-level carry scan
        float s = 0.0f, loc[16];
        if (tid < 64) {
            const int base = tid << 4;
            float v = 0.0f;
            #pragma unroll
            for (int i = 0; i < 16; i++) { v = fmaf(DECAY, v, pool[base + i]); loc[i] = v; }
            // warp-local scan of segment ends, factor decay^16
            s = v;
            float fp = DECAY16;
            #pragma unroll
            for (int off = 1; off < 32; off <<= 1) {
                float n = __shfl_up_sync(0xFFFFFFFFu, s, off);
                if ((tid & 31) >= off) s = fmaf(fp, n, s);
                fp *= fp;                        // underflow -> exact 0, fine
            }
            if (tid == 31) pool[1024] = s;       // total of first 512 (S31)
        }
        __syncthreads();
        if (tid < 64) {
            const int lane = tid & 31;
            float carry;
            if (tid < 32) {
                carry = __shfl_up_sync(0xFFFFFFFFu, s, 1);
                if (lane == 0) carry = 0.0f;
            } else {
                float pw = __shfl_up_sync(0xFFFFFFFFu, s, 1);
                if (lane == 0) pw = 0.0f;
                carry = fmaf(pool[1024], exp2f(L2F16 * (float)lane), pw);
            }
            float cs = carry;
            float* dst = plane + PAD + (tid << 4);
            #pragma unroll
            for (int i = 0; i < 16; i++) { cs *= DECAY; loc[i] += cs; }
            #pragma unroll
            for (int i = 0; i < 16; i += 4)
                *reinterpret_cast<float4*>(dst + i) =
                    make_float4(loc[i], loc[i+1], loc[i+2], loc[i+3]);
        }
        __threadfence();                         // publish plane + pad
        __syncthreads();
        if (tid == 0) atomicAdd(&g_done, 1);
        __syncthreads();                         // reuse pool below
    }

    // ---------------- Spin until all 32 channels are scanned ---------------
    if (tid == 0) {
        while (atomicAdd(&g_done, 0) < 32) { }
        __threadfence();
    }
    __syncthreads();

    // ---------------- Stage y windows: ybuf[f][j] = y_f[t0 - 256 + j] ------
    float* yb0 = pool;                           // [0, 272)
    float* yb1 = pool + WIN;                     // [272, 544)
    if (tid < 136) {
        const int pl = (tid >= 68);
        const int q  = pl ? tid - 68 : tid;      // float4 index 0..67
        const float4 v = *reinterpret_cast<const float4*>(
            g_y + ((pl ? NCH : 0) + nc) * YLEN + t0 + (q << 2));
        *reinterpret_cast<float4*>((pl ? yb1 : yb0) + (q << 2)) = v;
    }
    __syncthreads();

    // ---------------- Gather + combine + store -----------------------------
    // smem gather index j = tt + 256 - gd(k):
    //   d<256: j = tt + d + k (ascending in k), plane 1; j0 = tb + d
    //   d>=256: j = tt + 511 - d - k (descending), plane 0; j0 = tb + 508 - d
    const bool firstHalf = (d < 256);
    const float* gp = firstHalf ? yb1 : yb0;
    const float* bp = firstHalf ? yb0 : yb1;
    const int j0 = firstHalf ? (tb + d) : (tb + 508 - d);   // 16B aligned

    const float4 q0 = *reinterpret_cast<const float4*>(gp + j0);
    const float4 q1 = *reinterpret_cast<const float4*>(gp + j0 + 4);
    const float4 q2 = *reinterpret_cast<const float4*>(gp + j0 + 8);
    const float gr[12] = {q0.x,q0.y,q0.z,q0.w, q1.x,q1.y,q1.z,q1.w,
                          q2.x,q2.y,q2.z,q2.w};

    const float4 b0 = *reinterpret_cast<const float4*>(bp + 256 + tb);
    const float4 b1 = *reinterpret_cast<const float4*>(bp + 256 + tb + 4);
    const float bb[8] = {b0.x,b0.y,b0.z,b0.w, b1.x,b1.y,b1.z,b1.w};
    const float wv[4] = {w4.x, w4.y, w4.z, w4.w};

    float* op = out + ((t0 + tb) << 13) + (nc << 9) + d;

    if (firstHalf) {
        // gather reg index = i + k
        #pragma unroll
        for (int i = 0; i < 8; i++) {
            const float b = bb[i];
            float4 r = make_float4(wv[0] * (gr[i + 0] + b),
                                   wv[1] * (gr[i + 1] + b),
                                   wv[2] * (gr[i + 2] + b),
                                   wv[3] * (gr[i + 3] + b));
            *reinterpret_cast<float4*>(op + (i << 13)) = r;
        }
    } else {
        // gather reg index = i + (3 - k)
        #pragma unroll
        for (int i = 0; i < 8; i++) {
            const float b = bb[i];
            float4 r = make_float4(wv[0] * (gr[i + 3] + b),
                                   wv[1] * (gr[i + 2] + b),
                                   wv[2] * (gr[i + 1] + b),
                                   wv[3] * (gr[i + 0] + b));
            *reinterpret_cast<float4*>(op + (i << 13)) = r;
        }
    }

    // ---------------- Reset counters for next graph replay -----------------
    __syncthreads();
    if (tid == 0) {
        if (atomicAdd(&g_fin, 1) == NBLK - 1) {
            g_done = 0;
            g_fin  = 0;
        }
    }
}

// ---------------------------------------------------------------------------
extern "C" void kernel_launch(void* const* d_in, const int* in_sizes, int n_in,
                              void* d_out, int out_size) {
    const float* x      = (const float*)d_in[0];
    const float* weight = (const float*)d_in[1];
    float*       out    = (float*)d_out;

    jeffress_all<<<NBLK, 256>>>(x, weight, out);

    (void)in_sizes; (void)n_in; (void)out_size;
}